// round 1
// baseline (speedup 1.0000x reference)
#include <cuda_runtime.h>
#include <mma.h>
#include <math.h>
#include <type_traits>

using namespace nvcuda;

#define DIM_IO   1024
#define NHOST    4096
#define NGUEST   8192

// -------- scratch (device globals: allocation-free) --------
__device__ float g_query[(size_t)NHOST * DIM_IO];   // 16 MB
__device__ float g_key  [(size_t)NGUEST * DIM_IO];  // 32 MB
__device__ float g_value[(size_t)NGUEST * DIM_IO];  // 32 MB
__device__ float g_S    [(size_t)NHOST * NGUEST];   // 128 MB (logits, then probs in-place)

// ============================================================
// TF32 WMMA GEMM: C[M,N] = alpha * A[M,K] @ B
//   TRANS_B == false : B is [K,N] row-major
//   TRANS_B == true  : B is [N,K] row-major (compute A @ B^T)
// Tiles: BM=128, BN=128, BK=32; 8 warps, warp tile 32x64.
// ============================================================
template <bool TRANS_B>
__global__ void __launch_bounds__(256)
gemm_tf32(const float* __restrict__ A, const float* __restrict__ B,
          float* __restrict__ C, int M, int N, int K, float alpha)
{
    constexpr int BM = 128, BN = 128, BK = 32;
    constexpr int APAD = BK + 4;                 // 36
    constexpr int BSTRIDE_T = BK + 4;            // 36 (col-major view)
    constexpr int BSTRIDE_N = BN + 4;            // 132

    __shared__ float As[BM][APAD];
    __shared__ float Bs[4608];                   // max(128*36, 32*132) floats

    const int tid = threadIdx.x;
    const int wid = tid >> 5;
    const int wm  = wid >> 1;    // 0..3  -> 32 rows each
    const int wn  = wid & 1;     // 0..1  -> 64 cols each

    const int bm0 = blockIdx.y * BM;
    const int bn0 = blockIdx.x * BN;

    using FragA = wmma::fragment<wmma::matrix_a, 16, 16, 8, wmma::precision::tf32, wmma::row_major>;
    using BLay  = typename std::conditional<TRANS_B, wmma::col_major, wmma::row_major>::type;
    using FragB = wmma::fragment<wmma::matrix_b, 16, 16, 8, wmma::precision::tf32, BLay>;
    using FragC = wmma::fragment<wmma::accumulator, 16, 16, 8, float>;

    FragC acc[2][4];
    #pragma unroll
    for (int i = 0; i < 2; i++)
        #pragma unroll
        for (int j = 0; j < 4; j++)
            wmma::fill_fragment(acc[i][j], 0.0f);

    for (int k0 = 0; k0 < K; k0 += BK) {
        // ---- load A tile: 128 x 32, float4 along K ----
        #pragma unroll
        for (int t = 0; t < 4; t++) {
            int idx = tid + t * 256;             // 0..1023
            int r = idx >> 3;
            int c = (idx & 7) << 2;
            float4 v = *(const float4*)(A + (size_t)(bm0 + r) * K + k0 + c);
            float* dst = &As[r][c];
            dst[0] = v.x; dst[1] = v.y; dst[2] = v.z; dst[3] = v.w;
        }
        // ---- load B tile ----
        #pragma unroll
        for (int t = 0; t < 4; t++) {
            int idx = tid + t * 256;
            if (TRANS_B) {
                // B[N,K]: load rows along K, store [n][k] (col-major for frag)
                int n = idx >> 3;
                int c = (idx & 7) << 2;
                float4 v = *(const float4*)(B + (size_t)(bn0 + n) * K + k0 + c);
                float* dst = &Bs[n * BSTRIDE_T + c];
                dst[0] = v.x; dst[1] = v.y; dst[2] = v.z; dst[3] = v.w;
            } else {
                // B[K,N]: load rows along N, store [k][n]
                int r = idx >> 5;
                int c = (idx & 31) << 2;
                float4 v = *(const float4*)(B + (size_t)(k0 + r) * N + bn0 + c);
                float* dst = &Bs[r * BSTRIDE_N + c];
                dst[0] = v.x; dst[1] = v.y; dst[2] = v.z; dst[3] = v.w;
            }
        }
        __syncthreads();

        #pragma unroll
        for (int kk = 0; kk < BK; kk += 8) {
            FragA af[2];
            FragB bf[4];
            #pragma unroll
            for (int i = 0; i < 2; i++) {
                wmma::load_matrix_sync(af[i], &As[wm * 32 + i * 16][kk], APAD);
                #pragma unroll
                for (int e = 0; e < af[i].num_elements; e++)
                    af[i].x[e] = wmma::__float_to_tf32(af[i].x[e]);
            }
            #pragma unroll
            for (int j = 0; j < 4; j++) {
                if (TRANS_B) {
                    wmma::load_matrix_sync(bf[j], &Bs[(wn * 64 + j * 16) * BSTRIDE_T + kk], BSTRIDE_T);
                } else {
                    wmma::load_matrix_sync(bf[j], &Bs[kk * BSTRIDE_N + wn * 64 + j * 16], BSTRIDE_N);
                }
                #pragma unroll
                for (int e = 0; e < bf[j].num_elements; e++)
                    bf[j].x[e] = wmma::__float_to_tf32(bf[j].x[e]);
            }
            #pragma unroll
            for (int i = 0; i < 2; i++)
                #pragma unroll
                for (int j = 0; j < 4; j++)
                    wmma::mma_sync(acc[i][j], af[i], bf[j], acc[i][j]);
        }
        __syncthreads();
    }

    // ---- epilogue: scale + store ----
    #pragma unroll
    for (int i = 0; i < 2; i++) {
        #pragma unroll
        for (int j = 0; j < 4; j++) {
            #pragma unroll
            for (int e = 0; e < acc[i][j].num_elements; e++)
                acc[i][j].x[e] *= alpha;
            int row = bm0 + wm * 32 + i * 16;
            int col = bn0 + wn * 64 + j * 16;
            wmma::store_matrix_sync(&C[(size_t)row * N + col], acc[i][j], N, wmma::mem_row_major);
        }
    }
}

// ============================================================
// Row softmax, in place. One block per row (N = 8192).
// ============================================================
__global__ void __launch_bounds__(256)
softmax_rows(float* __restrict__ S, int Ncols)
{
    __shared__ float buf[NGUEST];
    __shared__ float redm[8];
    __shared__ float reds[8];

    const int tid = threadIdx.x;
    float* row = S + (size_t)blockIdx.x * Ncols;

    float lmax = -1e30f;
    for (int i = tid; i < Ncols; i += 256) {
        float v = row[i];
        buf[i] = v;
        lmax = fmaxf(lmax, v);
    }
    #pragma unroll
    for (int o = 16; o; o >>= 1)
        lmax = fmaxf(lmax, __shfl_xor_sync(0xffffffffu, lmax, o));
    if ((tid & 31) == 0) redm[tid >> 5] = lmax;
    __syncthreads();

    float m = redm[0];
    #pragma unroll
    for (int i = 1; i < 8; i++) m = fmaxf(m, redm[i]);

    float lsum = 0.0f;
    for (int i = tid; i < Ncols; i += 256) {
        float e = __expf(buf[i] - m);
        buf[i] = e;
        lsum += e;
    }
    #pragma unroll
    for (int o = 16; o; o >>= 1)
        lsum += __shfl_xor_sync(0xffffffffu, lsum, o);
    if ((tid & 31) == 0) reds[tid >> 5] = lsum;
    __syncthreads();

    float s = reds[0];
    #pragma unroll
    for (int i = 1; i < 8; i++) s += reds[i];
    float inv = 1.0f / s;

    for (int i = tid; i < Ncols; i += 256)
        row[i] = buf[i] * inv;
}

// ============================================================
// launch
// ============================================================
extern "C" void kernel_launch(void* const* d_in, const int* in_sizes, int n_in,
                              void* d_out, int out_size)
{
    const float* fh = (const float*)d_in[0];   // [4096, 1024]
    const float* fg = (const float*)d_in[1];   // [8192, 1024]
    const float* Qw = (const float*)d_in[2];   // [1024, 1024]
    const float* Kw = (const float*)d_in[3];
    const float* Vw = (const float*)d_in[4];
    float* out = (float*)d_out;                // [4096, 1024]

    void *pq, *pk, *pv, *ps;
    cudaGetSymbolAddress(&pq, g_query);
    cudaGetSymbolAddress(&pk, g_key);
    cudaGetSymbolAddress(&pv, g_value);
    cudaGetSymbolAddress(&ps, g_S);
    float* dq = (float*)pq;
    float* dk = (float*)pk;
    float* dv = (float*)pv;
    float* dS = (float*)ps;

    const float scale = 1.0f / 32.0f;  // 1/sqrt(1024)

    // projections
    gemm_tf32<false><<<dim3(DIM_IO / 128, NHOST  / 128), 256>>>(fh, Qw, dq, NHOST,  DIM_IO, DIM_IO, 1.0f);
    gemm_tf32<false><<<dim3(DIM_IO / 128, NGUEST / 128), 256>>>(fg, Kw, dk, NGUEST, DIM_IO, DIM_IO, 1.0f);
    gemm_tf32<false><<<dim3(DIM_IO / 128, NGUEST / 128), 256>>>(fg, Vw, dv, NGUEST, DIM_IO, DIM_IO, 1.0f);

    // logits = scale * query @ key^T
    gemm_tf32<true><<<dim3(NGUEST / 128, NHOST / 128), 256>>>(dq, dk, dS, NHOST, NGUEST, DIM_IO, scale);

    // softmax rows
    softmax_rows<<<NHOST, 256>>>(dS, NGUEST);

    // out = P @ value
    gemm_tf32<false><<<dim3(DIM_IO / 128, NHOST / 128), 256>>>(dS, dv, out, NHOST, DIM_IO, NGUEST, 1.0f);
}

// round 3
// speedup vs baseline: 1.2971x; 1.2971x over previous
#include <cuda_runtime.h>
#include <mma.h>
#include <cstdint>

using namespace nvcuda;

#define DIM_IO   1024
#define NHOST    4096
#define NGUEST   8192

// -------- scratch (device globals: allocation-free) --------
__device__ float g_fh   [(size_t)NHOST  * DIM_IO];   // rounded features_host
__device__ float g_fg   [(size_t)NGUEST * DIM_IO];   // rounded features_guests
__device__ float g_QwT  [(size_t)DIM_IO * DIM_IO];
__device__ float g_KwT  [(size_t)DIM_IO * DIM_IO];
__device__ float g_VwT  [(size_t)DIM_IO * DIM_IO];
__device__ float g_query[(size_t)NHOST  * DIM_IO];
__device__ float g_key  [(size_t)NGUEST * DIM_IO];
__device__ float g_valT [(size_t)DIM_IO * NGUEST];   // value^T [1024, 8192]
__device__ float g_S    [(size_t)NHOST  * NGUEST];   // logits -> probs

// ============================================================
// helpers
// ============================================================
__device__ __forceinline__ float tf32_rn(float v) {
    uint32_t b;
    asm("cvt.rna.tf32.f32 %0, %1;" : "=r"(b) : "f"(v));
    return __uint_as_float(b);
}
__device__ __forceinline__ void cp_async16(void* dst_smem, const void* src) {
    uint32_t a;
    asm("{ .reg .u64 t; cvta.to.shared.u64 t, %1; cvt.u32.u64 %0, t; }" : "=r"(a) : "l"(dst_smem));
    asm volatile("cp.async.cg.shared.global [%0], [%1], 16;" :: "r"(a), "l"(src) : "memory");
}
__device__ __forceinline__ void cp_commit() { asm volatile("cp.async.commit_group;" ::: "memory"); }
template <int N> __device__ __forceinline__ void cp_wait() {
    asm volatile("cp.async.wait_group %0;" :: "n"(N) : "memory");
}

// ============================================================
// tf32 WMMA GEMM (legacy tensor path, pipelined):
//   C[M,N] = alpha * A[M,K] @ B^T   with B:[N,K] row-major (both K-major)
// BM=128, BN=128, BK=32, 8 warps (warp tile 32x64), 3-stage cp.async.
// All inputs must already be exact-tf32 (no in-loop conversion).
// ============================================================
#define BM 128
#define BN 128
#define BK 32
#define LDT 36            // padded tile row (floats)
#define STAGE_FLOATS (2 * BM * LDT)       // A tile + B tile per stage
#define NSTAGES 3
#define GEMM_SMEM_BYTES (NSTAGES * STAGE_FLOATS * 4)   // 110592

__global__ void __launch_bounds__(256, 2)
gemm_tf32p(const float* __restrict__ A, const float* __restrict__ B,
           float* __restrict__ C, int M, int N, int K, float alpha, int round_out)
{
    extern __shared__ __align__(16) float smem[];

    const int tid = threadIdx.x;
    const int wid = tid >> 5;
    const int wm  = wid >> 1;     // 0..3  -> 32-row slice
    const int wn  = wid & 1;      // 0..1  -> 64-col slice
    const int bm0 = blockIdx.y * BM;
    const int bn0 = blockIdx.x * BN;
    const int niter = K / BK;

    using FragA = wmma::fragment<wmma::matrix_a, 16, 16, 8, wmma::precision::tf32, wmma::row_major>;
    using FragB = wmma::fragment<wmma::matrix_b, 16, 16, 8, wmma::precision::tf32, wmma::col_major>;
    using FragC = wmma::fragment<wmma::accumulator, 16, 16, 8, float>;

    FragC acc[2][4];
    #pragma unroll
    for (int i = 0; i < 2; i++)
        #pragma unroll
        for (int j = 0; j < 4; j++)
            wmma::fill_fragment(acc[i][j], 0.0f);

    // stage s: A at smem + s*STAGE_FLOATS, B at +BM*LDT
    auto load_stage = [&](int s, int kit) {
        float* As = smem + s * STAGE_FLOATS;
        float* Bs = As + BM * LDT;
        const int k0 = kit * BK;
        #pragma unroll
        for (int t = 0; t < 4; t++) {
            int idx = tid + t * 256;          // 0..1023
            int r = idx >> 3;
            int c = (idx & 7) << 2;           // float col 0,4,..,28
            cp_async16(As + r * LDT + c, A + (size_t)(bm0 + r) * K + k0 + c);
        }
        #pragma unroll
        for (int t = 0; t < 4; t++) {
            int idx = tid + t * 256;
            int r = idx >> 3;
            int c = (idx & 7) << 2;
            cp_async16(Bs + r * LDT + c, B + (size_t)(bn0 + r) * K + k0 + c);
        }
        cp_commit();
    };

    load_stage(0, 0);
    load_stage(1, 1);

    for (int i = 0; i < niter; i++) {
        // prefetch 2 ahead (buffer (i+2)%3 held stage i-1, finished last iter)
        if (i + 2 < niter) {
            load_stage((i + 2) % NSTAGES, i + 2);
            cp_wait<2>();
        } else if (i + 1 < niter) {
            cp_wait<1>();
        } else {
            cp_wait<0>();
        }
        __syncthreads();

        const float* As = smem + (i % NSTAGES) * STAGE_FLOATS;
        const float* Bs = As + BM * LDT;

        #pragma unroll
        for (int kk = 0; kk < BK; kk += 8) {
            FragA af[2];
            FragB bf[4];
            #pragma unroll
            for (int x = 0; x < 2; x++)
                wmma::load_matrix_sync(af[x], As + (wm * 32 + x * 16) * LDT + kk, LDT);
            #pragma unroll
            for (int j = 0; j < 4; j++)
                wmma::load_matrix_sync(bf[j], Bs + (wn * 64 + j * 16) * LDT + kk, LDT);
            #pragma unroll
            for (int x = 0; x < 2; x++)
                #pragma unroll
                for (int j = 0; j < 4; j++)
                    wmma::mma_sync(acc[x][j], af[x], bf[j], acc[x][j]);
        }
        __syncthreads();
    }

    // epilogue: scale (+ optional exact-tf32 round) and store
    #pragma unroll
    for (int x = 0; x < 2; x++) {
        #pragma unroll
        for (int j = 0; j < 4; j++) {
            #pragma unroll
            for (int e = 0; e < acc[x][j].num_elements; e++) {
                float v = acc[x][j].x[e] * alpha;
                if (round_out) v = tf32_rn(v);
                acc[x][j].x[e] = v;
            }
            int row = bm0 + wm * 32 + x * 16;
            int col = bn0 + wn * 64 + j * 16;
            wmma::store_matrix_sync(&C[(size_t)row * N + col], acc[x][j], N, wmma::mem_row_major);
        }
    }
}

// ============================================================
// weight transpose (1024x1024) + round to exact tf32
// ============================================================
__global__ void __launch_bounds__(256)
transpose_round(const float* __restrict__ in, float* __restrict__ out)
{
    __shared__ float t[32][33];
    int x = blockIdx.x * 32 + threadIdx.x;
    int y = blockIdx.y * 32 + threadIdx.y;
    #pragma unroll
    for (int j = 0; j < 32; j += 8)
        t[threadIdx.y + j][threadIdx.x] = in[(size_t)(y + j) * DIM_IO + x];
    __syncthreads();
    x = blockIdx.y * 32 + threadIdx.x;
    y = blockIdx.x * 32 + threadIdx.y;
    #pragma unroll
    for (int j = 0; j < 32; j += 8)
        out[(size_t)(y + j) * DIM_IO + x] = tf32_rn(t[threadIdx.x][threadIdx.y + j]);
}

// elementwise round-to-tf32 copy (float4)
__global__ void __launch_bounds__(256)
round_copy(const float4* __restrict__ in, float4* __restrict__ out, int n4)
{
    int i = blockIdx.x * 256 + threadIdx.x;
    if (i < n4) {
        float4 v = in[i];
        v.x = tf32_rn(v.x); v.y = tf32_rn(v.y);
        v.z = tf32_rn(v.z); v.w = tf32_rn(v.w);
        out[i] = v;
    }
}

// ============================================================
// Row softmax, in place, rounds output to exact tf32.
// ============================================================
__global__ void __launch_bounds__(256)
softmax_rows(float* __restrict__ S, int Ncols)
{
    __shared__ float buf[NGUEST];
    __shared__ float redm[8];
    __shared__ float reds[8];

    const int tid = threadIdx.x;
    float* row = S + (size_t)blockIdx.x * Ncols;

    float lmax = -1e30f;
    for (int i = tid; i < Ncols; i += 256) {
        float v = row[i];
        buf[i] = v;
        lmax = fmaxf(lmax, v);
    }
    #pragma unroll
    for (int o = 16; o; o >>= 1)
        lmax = fmaxf(lmax, __shfl_xor_sync(0xffffffffu, lmax, o));
    if ((tid & 31) == 0) redm[tid >> 5] = lmax;
    __syncthreads();

    float m = redm[0];
    #pragma unroll
    for (int i = 1; i < 8; i++) m = fmaxf(m, redm[i]);

    float lsum = 0.0f;
    for (int i = tid; i < Ncols; i += 256) {
        float e = __expf(buf[i] - m);
        buf[i] = e;
        lsum += e;
    }
    #pragma unroll
    for (int o = 16; o; o >>= 1)
        lsum += __shfl_xor_sync(0xffffffffu, lsum, o);
    if ((tid & 31) == 0) reds[tid >> 5] = lsum;
    __syncthreads();

    float s = reds[0];
    #pragma unroll
    for (int i = 1; i < 8; i++) s += reds[i];
    float inv = 1.0f / s;

    for (int i = tid; i < Ncols; i += 256)
        row[i] = tf32_rn(buf[i] * inv);
}

// ============================================================
// launch
// ============================================================
extern "C" void kernel_launch(void* const* d_in, const int* in_sizes, int n_in,
                              void* d_out, int out_size)
{
    const float* fh = (const float*)d_in[0];   // [4096, 1024]
    const float* fg = (const float*)d_in[1];   // [8192, 1024]
    const float* Qw = (const float*)d_in[2];   // [1024, 1024]
    const float* Kw = (const float*)d_in[3];
    const float* Vw = (const float*)d_in[4];
    float* out = (float*)d_out;                // [4096, 1024]

    void *p;
    cudaGetSymbolAddress(&p, g_fh);    float* dfh = (float*)p;
    cudaGetSymbolAddress(&p, g_fg);    float* dfg = (float*)p;
    cudaGetSymbolAddress(&p, g_QwT);   float* dQwT = (float*)p;
    cudaGetSymbolAddress(&p, g_KwT);   float* dKwT = (float*)p;
    cudaGetSymbolAddress(&p, g_VwT);   float* dVwT = (float*)p;
    cudaGetSymbolAddress(&p, g_query); float* dq = (float*)p;
    cudaGetSymbolAddress(&p, g_key);   float* dk = (float*)p;
    cudaGetSymbolAddress(&p, g_valT);  float* dvt = (float*)p;
    cudaGetSymbolAddress(&p, g_S);     float* dS = (float*)p;

    static bool attr_set = false;
    if (!attr_set) {
        cudaFuncSetAttribute(gemm_tf32p, cudaFuncAttributeMaxDynamicSharedMemorySize, GEMM_SMEM_BYTES);
        attr_set = true;
    }

    const float scale = 1.0f / 32.0f;  // 1/sqrt(1024)

    // pre-round inputs to exact tf32
    round_copy<<<NHOST  * DIM_IO / 4 / 256, 256>>>((const float4*)fh, (float4*)dfh, NHOST  * DIM_IO / 4);
    round_copy<<<NGUEST * DIM_IO / 4 / 256, 256>>>((const float4*)fg, (float4*)dfg, NGUEST * DIM_IO / 4);

    dim3 tb(32, 8), tg(32, 32);
    transpose_round<<<tg, tb>>>(Qw, dQwT);
    transpose_round<<<tg, tb>>>(Kw, dKwT);
    transpose_round<<<tg, tb>>>(Vw, dVwT);

    // query = fh @ Qw = fh @ (QwT)^T            [4096,1024]
    gemm_tf32p<<<dim3(DIM_IO / BN, NHOST / BM), 256, GEMM_SMEM_BYTES>>>(
        dfh, dQwT, dq, NHOST, DIM_IO, DIM_IO, 1.0f, 1);
    // key = fg @ Kw                             [8192,1024]
    gemm_tf32p<<<dim3(DIM_IO / BN, NGUEST / BM), 256, GEMM_SMEM_BYTES>>>(
        dfg, dKwT, dk, NGUEST, DIM_IO, DIM_IO, 1.0f, 1);
    // value^T = VwT @ fg^T                      [1024,8192]
    gemm_tf32p<<<dim3(NGUEST / BN, DIM_IO / BM), 256, GEMM_SMEM_BYTES>>>(
        dVwT, dfg, dvt, DIM_IO, NGUEST, DIM_IO, 1.0f, 1);
    // logits = scale * query @ key^T            [4096,8192]
    gemm_tf32p<<<dim3(NGUEST / BN, NHOST / BM), 256, GEMM_SMEM_BYTES>>>(
        dq, dk, dS, NHOST, NGUEST, DIM_IO, scale, 0);
    // softmax rows (writes tf32-rounded probs)
    softmax_rows<<<NHOST, 256>>>(dS, NGUEST);
    // out = P @ value = P @ (valT)^T            [4096,1024]
    gemm_tf32p<<<dim3(DIM_IO / BN, NHOST / BM), 256, GEMM_SMEM_BYTES>>>(
        dS, dvt, out, NHOST, DIM_IO, NGUEST, 1.0f, 0);
}

// round 4
// speedup vs baseline: 4.7417x; 3.6557x over previous
#include <cuda_runtime.h>
#include <cuda_fp16.h>
#include <mma.h>
#include <cstdint>

using namespace nvcuda;

#define DIM_IO   1024
#define NHOST    4096
#define NGUEST   8192

// -------- scratch (device globals: allocation-free) --------
__device__ __half g_fh  [(size_t)NHOST  * DIM_IO];   // fp16 features_host
__device__ __half g_fg  [(size_t)NGUEST * DIM_IO];   // fp16 features_guests
__device__ __half g_QwT [(size_t)DIM_IO * DIM_IO];
__device__ __half g_KwT [(size_t)DIM_IO * DIM_IO];
__device__ __half g_VwT [(size_t)DIM_IO * DIM_IO];
__device__ __half g_qh  [(size_t)NHOST  * DIM_IO];   // fp16 query
__device__ __half g_kh  [(size_t)NGUEST * DIM_IO];   // fp16 key
__device__ __half g_vth [(size_t)DIM_IO * NGUEST];   // fp16 value^T [1024, 8192]
__device__ __half g_P   [(size_t)NHOST  * NGUEST];   // fp16 probs
__device__ float  g_S   [(size_t)NHOST  * NGUEST];   // fp32 logits
__device__ float  g_tmp [(size_t)DIM_IO * NGUEST];   // fp32 GEMM staging (32 MB)

// ============================================================
// helpers
// ============================================================
__device__ __forceinline__ void cp_async16(void* dst_smem, const void* src) {
    uint32_t a;
    asm("{ .reg .u64 t; cvta.to.shared.u64 t, %1; cvt.u32.u64 %0, t; }" : "=r"(a) : "l"(dst_smem));
    asm volatile("cp.async.cg.shared.global [%0], [%1], 16;" :: "r"(a), "l"(src) : "memory");
}
__device__ __forceinline__ void cp_commit() { asm volatile("cp.async.commit_group;" ::: "memory"); }
template <int N> __device__ __forceinline__ void cp_wait() {
    asm volatile("cp.async.wait_group %0;" :: "n"(N) : "memory");
}

// ============================================================
// fp16 WMMA GEMM (pipelined): C[M,N] = alpha * A[M,K] @ B^T
//   A:[M,K] half, B:[N,K] half (both K-major), C:[M,N] float.
// BM=128, BN=128, BK=32, 8 warps (warp tile 32x64), 3-stage cp.async.
// ============================================================
#define BM 128
#define BN 128
#define BK 32
#define LDT 40                                   // padded row (halfs), 80B
#define STAGE_HALFS (2 * BM * LDT)               // A + B per stage
#define NSTAGES 3
#define GEMM_SMEM_BYTES (NSTAGES * STAGE_HALFS * 2)   // 61440

__global__ void __launch_bounds__(256, 2)
gemm_h(const __half* __restrict__ A, const __half* __restrict__ B,
       float* __restrict__ C, int M, int N, int K, float alpha)
{
    extern __shared__ __align__(16) __half smem[];

    const int tid = threadIdx.x;
    const int wid = tid >> 5;
    const int wm  = wid >> 1;     // 0..3  -> 32-row slice
    const int wn  = wid & 1;      // 0..1  -> 64-col slice
    const int bm0 = blockIdx.y * BM;
    const int bn0 = blockIdx.x * BN;
    const int niter = K / BK;

    using FragA = wmma::fragment<wmma::matrix_a, 16, 16, 16, __half, wmma::row_major>;
    using FragB = wmma::fragment<wmma::matrix_b, 16, 16, 16, __half, wmma::col_major>;
    using FragC = wmma::fragment<wmma::accumulator, 16, 16, 16, float>;

    FragC acc[2][4];
    #pragma unroll
    for (int i = 0; i < 2; i++)
        #pragma unroll
        for (int j = 0; j < 4; j++)
            wmma::fill_fragment(acc[i][j], 0.0f);

    auto load_stage = [&](int s, int kit) {
        __half* As = smem + s * STAGE_HALFS;
        __half* Bs = As + BM * LDT;
        const int k0 = kit * BK;
        #pragma unroll
        for (int t = 0; t < 2; t++) {
            int idx = tid + t * 256;          // 0..511
            int r = idx >> 2;
            int c = (idx & 3) << 3;           // half col 0,8,16,24
            cp_async16(As + r * LDT + c, A + (size_t)(bm0 + r) * K + k0 + c);
        }
        #pragma unroll
        for (int t = 0; t < 2; t++) {
            int idx = tid + t * 256;
            int r = idx >> 2;
            int c = (idx & 3) << 3;
            cp_async16(Bs + r * LDT + c, B + (size_t)(bn0 + r) * K + k0 + c);
        }
        cp_commit();
    };

    load_stage(0, 0);
    load_stage(1, 1);

    for (int i = 0; i < niter; i++) {
        if (i + 2 < niter) {
            load_stage((i + 2) % NSTAGES, i + 2);
            cp_wait<2>();
        } else if (i + 1 < niter) {
            cp_wait<1>();
        } else {
            cp_wait<0>();
        }
        __syncthreads();

        const __half* As = smem + (i % NSTAGES) * STAGE_HALFS;
        const __half* Bs = As + BM * LDT;

        #pragma unroll
        for (int kk = 0; kk < BK; kk += 16) {
            FragA af[2];
            FragB bf[4];
            #pragma unroll
            for (int x = 0; x < 2; x++)
                wmma::load_matrix_sync(af[x], As + (wm * 32 + x * 16) * LDT + kk, LDT);
            #pragma unroll
            for (int j = 0; j < 4; j++)
                wmma::load_matrix_sync(bf[j], Bs + (wn * 64 + j * 16) * LDT + kk, LDT);
            #pragma unroll
            for (int x = 0; x < 2; x++)
                #pragma unroll
                for (int j = 0; j < 4; j++)
                    wmma::mma_sync(acc[x][j], af[x], bf[j], acc[x][j]);
        }
        __syncthreads();
    }

    #pragma unroll
    for (int x = 0; x < 2; x++) {
        #pragma unroll
        for (int j = 0; j < 4; j++) {
            #pragma unroll
            for (int e = 0; e < acc[x][j].num_elements; e++)
                acc[x][j].x[e] *= alpha;
            int row = bm0 + wm * 32 + x * 16;
            int col = bn0 + wn * 64 + j * 16;
            wmma::store_matrix_sync(&C[(size_t)row * N + col], acc[x][j], N, wmma::mem_row_major);
        }
    }
}

// ============================================================
// fp32 -> fp16 convert (float4 -> 8B)
// ============================================================
__global__ void __launch_bounds__(256)
f32_to_f16(const float4* __restrict__ in, __half2* __restrict__ out, int n4)
{
    int i = blockIdx.x * 256 + threadIdx.x;
    if (i < n4) {
        float4 v = in[i];
        out[2 * i]     = __floats2half2_rn(v.x, v.y);
        out[2 * i + 1] = __floats2half2_rn(v.z, v.w);
    }
}

// ============================================================
// weight transpose (1024x1024) fp32 -> fp16
// ============================================================
__global__ void __launch_bounds__(256)
transpose_h(const float* __restrict__ in, __half* __restrict__ out)
{
    __shared__ float t[32][33];
    int x = blockIdx.x * 32 + threadIdx.x;
    int y = blockIdx.y * 32 + threadIdx.y;
    #pragma unroll
    for (int j = 0; j < 32; j += 8)
        t[threadIdx.y + j][threadIdx.x] = in[(size_t)(y + j) * DIM_IO + x];
    __syncthreads();
    x = blockIdx.y * 32 + threadIdx.x;
    y = blockIdx.x * 32 + threadIdx.y;
    #pragma unroll
    for (int j = 0; j < 32; j += 8)
        out[(size_t)(y + j) * DIM_IO + x] = __float2half_rn(t[threadIdx.x][threadIdx.y + j]);
}

// ============================================================
// Row softmax: read fp32 logits, write fp16 probs.
// ============================================================
__global__ void __launch_bounds__(256)
softmax_rows(const float* __restrict__ S, __half* __restrict__ P, int Ncols)
{
    __shared__ float buf[NGUEST];
    __shared__ float redm[8];
    __shared__ float reds[8];

    const int tid = threadIdx.x;
    const float* row = S + (size_t)blockIdx.x * Ncols;
    __half* prow = P + (size_t)blockIdx.x * Ncols;

    float lmax = -1e30f;
    for (int i = tid; i < Ncols; i += 256) {
        float v = row[i];
        buf[i] = v;
        lmax = fmaxf(lmax, v);
    }
    #pragma unroll
    for (int o = 16; o; o >>= 1)
        lmax = fmaxf(lmax, __shfl_xor_sync(0xffffffffu, lmax, o));
    if ((tid & 31) == 0) redm[tid >> 5] = lmax;
    __syncthreads();

    float m = redm[0];
    #pragma unroll
    for (int i = 1; i < 8; i++) m = fmaxf(m, redm[i]);

    float lsum = 0.0f;
    for (int i = tid; i < Ncols; i += 256) {
        float e = __expf(buf[i] - m);
        buf[i] = e;
        lsum += e;
    }
    #pragma unroll
    for (int o = 16; o; o >>= 1)
        lsum += __shfl_xor_sync(0xffffffffu, lsum, o);
    if ((tid & 31) == 0) reds[tid >> 5] = lsum;
    __syncthreads();

    float s = reds[0];
    #pragma unroll
    for (int i = 1; i < 8; i++) s += reds[i];
    float inv = 1.0f / s;

    for (int i = tid; i < Ncols; i += 256)
        prow[i] = __float2half_rn(buf[i] * inv);
}

// ============================================================
// launch
// ============================================================
extern "C" void kernel_launch(void* const* d_in, const int* in_sizes, int n_in,
                              void* d_out, int out_size)
{
    const float* fh = (const float*)d_in[0];   // [4096, 1024]
    const float* fg = (const float*)d_in[1];   // [8192, 1024]
    const float* Qw = (const float*)d_in[2];   // [1024, 1024]
    const float* Kw = (const float*)d_in[3];
    const float* Vw = (const float*)d_in[4];
    float* out = (float*)d_out;                // [4096, 1024]

    void *p;
    cudaGetSymbolAddress(&p, g_fh);  __half* hfh  = (__half*)p;
    cudaGetSymbolAddress(&p, g_fg);  __half* hfg  = (__half*)p;
    cudaGetSymbolAddress(&p, g_QwT); __half* hQwT = (__half*)p;
    cudaGetSymbolAddress(&p, g_KwT); __half* hKwT = (__half*)p;
    cudaGetSymbolAddress(&p, g_VwT); __half* hVwT = (__half*)p;
    cudaGetSymbolAddress(&p, g_qh);  __half* hq   = (__half*)p;
    cudaGetSymbolAddress(&p, g_kh);  __half* hk   = (__half*)p;
    cudaGetSymbolAddress(&p, g_vth); __half* hvt  = (__half*)p;
    cudaGetSymbolAddress(&p, g_P);   __half* hP   = (__half*)p;
    cudaGetSymbolAddress(&p, g_S);   float*  dS   = (float*)p;
    cudaGetSymbolAddress(&p, g_tmp); float*  dtmp = (float*)p;

    cudaFuncSetAttribute(gemm_h, cudaFuncAttributeMaxDynamicSharedMemorySize, GEMM_SMEM_BYTES);

    const float scale = 1.0f / 32.0f;  // 1/sqrt(1024)

    // inputs -> fp16
    f32_to_f16<<<NHOST  * DIM_IO / 4 / 256, 256>>>((const float4*)fh, (__half2*)hfh, NHOST  * DIM_IO / 4);
    f32_to_f16<<<NGUEST * DIM_IO / 4 / 256, 256>>>((const float4*)fg, (__half2*)hfg, NGUEST * DIM_IO / 4);

    dim3 tb(32, 8), tg(32, 32);
    transpose_h<<<tg, tb>>>(Qw, hQwT);
    transpose_h<<<tg, tb>>>(Kw, hKwT);
    transpose_h<<<tg, tb>>>(Vw, hVwT);

    // query = fh @ Qw            [4096,1024] -> fp16
    gemm_h<<<dim3(DIM_IO / BN, NHOST / BM), 256, GEMM_SMEM_BYTES>>>(
        hfh, hQwT, dtmp, NHOST, DIM_IO, DIM_IO, 1.0f);
    f32_to_f16<<<NHOST * DIM_IO / 4 / 256, 256>>>((const float4*)dtmp, (__half2*)hq, NHOST * DIM_IO / 4);

    // key = fg @ Kw              [8192,1024] -> fp16
    gemm_h<<<dim3(DIM_IO / BN, NGUEST / BM), 256, GEMM_SMEM_BYTES>>>(
        hfg, hKwT, dtmp, NGUEST, DIM_IO, DIM_IO, 1.0f);
    f32_to_f16<<<NGUEST * DIM_IO / 4 / 256, 256>>>((const float4*)dtmp, (__half2*)hk, NGUEST * DIM_IO / 4);

    // value^T = VwT @ fg^T       [1024,8192] -> fp16
    gemm_h<<<dim3(NGUEST / BN, DIM_IO / BM), 256, GEMM_SMEM_BYTES>>>(
        hVwT, hfg, dtmp, DIM_IO, NGUEST, DIM_IO, 1.0f);
    f32_to_f16<<<DIM_IO * NGUEST / 4 / 256, 256>>>((const float4*)dtmp, (__half2*)hvt, DIM_IO * NGUEST / 4);

    // logits = scale * query @ key^T   [4096,8192] fp32
    gemm_h<<<dim3(NGUEST / BN, NHOST / BM), 256, GEMM_SMEM_BYTES>>>(
        hq, hk, dS, NHOST, NGUEST, DIM_IO, scale);

    // softmax rows -> fp16 probs
    softmax_rows<<<NHOST, 256>>>(dS, hP, NGUEST);

    // out = P @ value = P @ (valT)^T   [4096,1024] fp32
    gemm_h<<<dim3(DIM_IO / BN, NHOST / BM), 256, GEMM_SMEM_BYTES>>>(
        hP, hvt, out, NHOST, DIM_IO, NGUEST, 1.0f);
}

// round 5
// speedup vs baseline: 4.9992x; 1.0543x over previous
#include <cuda_runtime.h>
#include <cuda_fp16.h>
#include <mma.h>
#include <cstdint>

using namespace nvcuda;

#define DIM_IO   1024
#define NHOST    4096
#define NGUEST   8192

// -------- scratch (device globals: allocation-free) --------
__device__ __half g_fh  [(size_t)NHOST  * DIM_IO];   // fp16 features_host
__device__ __half g_fg  [(size_t)NGUEST * DIM_IO];   // fp16 features_guests
__device__ __half g_QwT [(size_t)DIM_IO * DIM_IO];
__device__ __half g_KwT [(size_t)DIM_IO * DIM_IO];
__device__ __half g_VwT [(size_t)DIM_IO * DIM_IO];
__device__ __half g_qh  [(size_t)NHOST  * DIM_IO];   // fp16 query (pre-scaled by 1/32)
__device__ __half g_kh  [(size_t)NGUEST * DIM_IO];   // fp16 key
__device__ __half g_vth [(size_t)DIM_IO * NGUEST];   // fp16 value^T [1024, 8192]
__device__ __half g_P   [(size_t)NHOST  * NGUEST];   // fp16 probs
__device__ float  g_S   [(size_t)NHOST  * NGUEST];   // fp32 logits

// ============================================================
// helpers
// ============================================================
__device__ __forceinline__ void cp_async16(void* dst_smem, const void* src) {
    uint32_t a;
    asm("{ .reg .u64 t; cvta.to.shared.u64 t, %1; cvt.u32.u64 %0, t; }" : "=r"(a) : "l"(dst_smem));
    asm volatile("cp.async.cg.shared.global [%0], [%1], 16;" :: "r"(a), "l"(src) : "memory");
}
__device__ __forceinline__ void cp_commit() { asm volatile("cp.async.commit_group;" ::: "memory"); }
template <int N> __device__ __forceinline__ void cp_wait() {
    asm volatile("cp.async.wait_group %0;" :: "n"(N) : "memory");
}

// ============================================================
// fp16 WMMA GEMM (pipelined): C[M,N] = alpha * A[M,K] @ B^T
//   A:[M,K] half, B:[N,K] half (both K-major). OutT = float or __half.
// BM=128, BN=128, BK=64, 8 warps (warp tile 32x64), 2-stage cp.async.
// LDT=72 halfs (144B row): ldmatrix conflict-free (stride = 4 banks).
// ============================================================
#define BM 128
#define BN 128
#define BKG 64
#define LDT 72
#define STAGE_HALFS (2 * BM * LDT)               // A + B per stage = 18432 halfs
#define NSTAGES 2
#define GEMM_SMEM_BYTES (NSTAGES * STAGE_HALFS * 2)   // 73728

template <typename OutT>
__global__ void __launch_bounds__(256, 2)
gemm_h(const __half* __restrict__ A, const __half* __restrict__ B,
       OutT* __restrict__ C, int M, int N, int K, float alpha)
{
    extern __shared__ __align__(16) __half smem[];

    const int tid = threadIdx.x;
    const int wid = tid >> 5;
    const int wm  = wid >> 1;     // 0..3  -> 32-row slice
    const int wn  = wid & 1;      // 0..1  -> 64-col slice
    const int bm0 = blockIdx.y * BM;
    const int bn0 = blockIdx.x * BN;
    const int niter = K / BKG;

    using FragA  = wmma::fragment<wmma::matrix_a, 16, 16, 16, __half, wmma::row_major>;
    using FragB  = wmma::fragment<wmma::matrix_b, 16, 16, 16, __half, wmma::col_major>;
    using FragC  = wmma::fragment<wmma::accumulator, 16, 16, 16, float>;
    using FragCH = wmma::fragment<wmma::accumulator, 16, 16, 16, __half>;

    FragC acc[2][4];
    #pragma unroll
    for (int i = 0; i < 2; i++)
        #pragma unroll
        for (int j = 0; j < 4; j++)
            wmma::fill_fragment(acc[i][j], 0.0f);

    // stage: A[128][72] then B[128][72] (64 halfs data + pad)
    auto load_stage = [&](int s, int kit) {
        __half* As = smem + s * STAGE_HALFS;
        __half* Bs = As + BM * LDT;
        const int k0 = kit * BKG;
        #pragma unroll
        for (int t = 0; t < 4; t++) {
            int idx = tid + t * 256;          // 0..1023
            int r = idx >> 3;
            int c = (idx & 7) << 3;           // half col 0,8,...,56
            cp_async16(As + r * LDT + c, A + (size_t)(bm0 + r) * K + k0 + c);
        }
        #pragma unroll
        for (int t = 0; t < 4; t++) {
            int idx = tid + t * 256;
            int r = idx >> 3;
            int c = (idx & 7) << 3;
            cp_async16(Bs + r * LDT + c, B + (size_t)(bn0 + r) * K + k0 + c);
        }
        cp_commit();
    };

    load_stage(0, 0);
    if (niter > 1) load_stage(1, 1);

    for (int i = 0; i < niter; i++) {
        if (i + 1 < niter) cp_wait<1>(); else cp_wait<0>();
        __syncthreads();

        const __half* As = smem + (i % NSTAGES) * STAGE_HALFS;
        const __half* Bs = As + BM * LDT;

        #pragma unroll
        for (int kk = 0; kk < BKG; kk += 16) {
            FragA af[2];
            FragB bf[4];
            #pragma unroll
            for (int x = 0; x < 2; x++)
                wmma::load_matrix_sync(af[x], As + (wm * 32 + x * 16) * LDT + kk, LDT);
            #pragma unroll
            for (int j = 0; j < 4; j++)
                wmma::load_matrix_sync(bf[j], Bs + (wn * 64 + j * 16) * LDT + kk, LDT);
            #pragma unroll
            for (int x = 0; x < 2; x++)
                #pragma unroll
                for (int j = 0; j < 4; j++)
                    wmma::mma_sync(acc[x][j], af[x], bf[j], acc[x][j]);
        }
        __syncthreads();

        if (i + 2 < niter) load_stage(i % NSTAGES, i + 2);
    }

    // epilogue
    #pragma unroll
    for (int x = 0; x < 2; x++) {
        #pragma unroll
        for (int j = 0; j < 4; j++) {
            int row = bm0 + wm * 32 + x * 16;
            int col = bn0 + wn * 64 + j * 16;
            if constexpr (sizeof(OutT) == 2) {
                FragCH h;
                #pragma unroll
                for (int e = 0; e < acc[x][j].num_elements; e++)
                    h.x[e] = __float2half_rn(acc[x][j].x[e] * alpha);
                wmma::store_matrix_sync((__half*)&C[(size_t)row * N + col], h, N, wmma::mem_row_major);
            } else {
                #pragma unroll
                for (int e = 0; e < acc[x][j].num_elements; e++)
                    acc[x][j].x[e] *= alpha;
                wmma::store_matrix_sync((float*)&C[(size_t)row * N + col], acc[x][j], N, wmma::mem_row_major);
            }
        }
    }
}

// ============================================================
// fp32 -> fp16 convert with scale (float4 -> 8B)
// ============================================================
__global__ void __launch_bounds__(256)
f32_to_f16(const float4* __restrict__ in, __half2* __restrict__ out, int n4, float s)
{
    int i = blockIdx.x * 256 + threadIdx.x;
    if (i < n4) {
        float4 v = in[i];
        out[2 * i]     = __floats2half2_rn(v.x * s, v.y * s);
        out[2 * i + 1] = __floats2half2_rn(v.z * s, v.w * s);
    }
}

// ============================================================
// weight transpose (1024x1024) fp32 -> fp16
// ============================================================
__global__ void __launch_bounds__(256)
transpose_h(const float* __restrict__ in, __half* __restrict__ out)
{
    __shared__ float t[32][33];
    int x = blockIdx.x * 32 + threadIdx.x;
    int y = blockIdx.y * 32 + threadIdx.y;
    #pragma unroll
    for (int j = 0; j < 32; j += 8)
        t[threadIdx.y + j][threadIdx.x] = in[(size_t)(y + j) * DIM_IO + x];
    __syncthreads();
    x = blockIdx.y * 32 + threadIdx.x;
    y = blockIdx.x * 32 + threadIdx.y;
    #pragma unroll
    for (int j = 0; j < 32; j += 8)
        out[(size_t)(y + j) * DIM_IO + x] = __float2half_rn(t[threadIdx.x][threadIdx.y + j]);
}

// ============================================================
// Row softmax: read fp32 logits, write fp16 probs.
// ============================================================
__global__ void __launch_bounds__(256)
softmax_rows(const float* __restrict__ S, __half* __restrict__ P, int Ncols)
{
    __shared__ float buf[NGUEST];
    __shared__ float redm[8];
    __shared__ float reds[8];

    const int tid = threadIdx.x;
    const float* row = S + (size_t)blockIdx.x * Ncols;
    __half* prow = P + (size_t)blockIdx.x * Ncols;

    float lmax = -1e30f;
    for (int i = tid; i < Ncols; i += 256) {
        float v = row[i];
        buf[i] = v;
        lmax = fmaxf(lmax, v);
    }
    #pragma unroll
    for (int o = 16; o; o >>= 1)
        lmax = fmaxf(lmax, __shfl_xor_sync(0xffffffffu, lmax, o));
    if ((tid & 31) == 0) redm[tid >> 5] = lmax;
    __syncthreads();

    float m = redm[0];
    #pragma unroll
    for (int i = 1; i < 8; i++) m = fmaxf(m, redm[i]);

    float lsum = 0.0f;
    for (int i = tid; i < Ncols; i += 256) {
        float e = __expf(buf[i] - m);
        buf[i] = e;
        lsum += e;
    }
    #pragma unroll
    for (int o = 16; o; o >>= 1)
        lsum += __shfl_xor_sync(0xffffffffu, lsum, o);
    if ((tid & 31) == 0) reds[tid >> 5] = lsum;
    __syncthreads();

    float s = reds[0];
    #pragma unroll
    for (int i = 1; i < 8; i++) s += reds[i];
    float inv = 1.0f / s;

    for (int i = tid; i < Ncols; i += 256)
        prow[i] = __float2half_rn(buf[i] * inv);
}

// ============================================================
// launch
// ============================================================
extern "C" void kernel_launch(void* const* d_in, const int* in_sizes, int n_in,
                              void* d_out, int out_size)
{
    const float* fh = (const float*)d_in[0];   // [4096, 1024]
    const float* fg = (const float*)d_in[1];   // [8192, 1024]
    const float* Qw = (const float*)d_in[2];   // [1024, 1024]
    const float* Kw = (const float*)d_in[3];
    const float* Vw = (const float*)d_in[4];
    float* out = (float*)d_out;                // [4096, 1024]

    void *p;
    cudaGetSymbolAddress(&p, g_fh);  __half* hfh  = (__half*)p;
    cudaGetSymbolAddress(&p, g_fg);  __half* hfg  = (__half*)p;
    cudaGetSymbolAddress(&p, g_QwT); __half* hQwT = (__half*)p;
    cudaGetSymbolAddress(&p, g_KwT); __half* hKwT = (__half*)p;
    cudaGetSymbolAddress(&p, g_VwT); __half* hVwT = (__half*)p;
    cudaGetSymbolAddress(&p, g_qh);  __half* hq   = (__half*)p;
    cudaGetSymbolAddress(&p, g_kh);  __half* hk   = (__half*)p;
    cudaGetSymbolAddress(&p, g_vth); __half* hvt  = (__half*)p;
    cudaGetSymbolAddress(&p, g_P);   __half* hP   = (__half*)p;
    cudaGetSymbolAddress(&p, g_S);   float*  dS   = (float*)p;

    cudaFuncSetAttribute(gemm_h<float>,  cudaFuncAttributeMaxDynamicSharedMemorySize, GEMM_SMEM_BYTES);
    cudaFuncSetAttribute(gemm_h<__half>, cudaFuncAttributeMaxDynamicSharedMemorySize, GEMM_SMEM_BYTES);

    const float scale = 1.0f / 32.0f;  // 1/sqrt(1024)

    // inputs -> fp16
    f32_to_f16<<<NHOST  * DIM_IO / 4 / 256, 256>>>((const float4*)fh, (__half2*)hfh, NHOST  * DIM_IO / 4, 1.0f);
    f32_to_f16<<<NGUEST * DIM_IO / 4 / 256, 256>>>((const float4*)fg, (__half2*)hfg, NGUEST * DIM_IO / 4, 1.0f);

    dim3 tb(32, 8), tg(32, 32);
    transpose_h<<<tg, tb>>>(Qw, hQwT);
    transpose_h<<<tg, tb>>>(Kw, hKwT);
    transpose_h<<<tg, tb>>>(Vw, hVwT);

    // query = (fh @ Qw) * scale        [4096,1024] fp16 (scale folded here)
    gemm_h<__half><<<dim3(DIM_IO / BN, NHOST / BM), 256, GEMM_SMEM_BYTES>>>(
        hfh, hQwT, hq, NHOST, DIM_IO, DIM_IO, scale);
    // key = fg @ Kw                    [8192,1024] fp16
    gemm_h<__half><<<dim3(DIM_IO / BN, NGUEST / BM), 256, GEMM_SMEM_BYTES>>>(
        hfg, hKwT, hk, NGUEST, DIM_IO, DIM_IO, 1.0f);
    // value^T = VwT @ fg^T             [1024,8192] fp16
    gemm_h<__half><<<dim3(NGUEST / BN, DIM_IO / BM), 256, GEMM_SMEM_BYTES>>>(
        hVwT, hfg, hvt, DIM_IO, NGUEST, DIM_IO, 1.0f);
    // logits = query_scaled @ key^T    [4096,8192] fp32
    gemm_h<float><<<dim3(NGUEST / BN, NHOST / BM), 256, GEMM_SMEM_BYTES>>>(
        hq, hk, dS, NHOST, NGUEST, DIM_IO, 1.0f);
    // softmax rows -> fp16 probs
    softmax_rows<<<NHOST, 256>>>(dS, hP, NGUEST);
    // out = P @ value = P @ (valT)^T   [4096,1024] fp32
    gemm_h<float><<<dim3(DIM_IO / BN, NHOST / BM), 256, GEMM_SMEM_BYTES>>>(
        hP, hvt, out, NHOST, DIM_IO, NGUEST, 1.0f);
}

// round 6
// speedup vs baseline: 5.2346x; 1.0471x over previous
#include <cuda_runtime.h>
#include <cuda_fp16.h>
#include <mma.h>
#include <cstdint>

using namespace nvcuda;

#define DIM_IO   1024
#define NHOST    4096
#define NGUEST   8192

// -------- scratch (device globals: allocation-free) --------
__device__ __half g_fh  [(size_t)NHOST  * DIM_IO];
__device__ __half g_fg  [(size_t)NGUEST * DIM_IO];
__device__ __half g_QwT [(size_t)DIM_IO * DIM_IO];
__device__ __half g_KwT [(size_t)DIM_IO * DIM_IO];
__device__ __half g_VwT [(size_t)DIM_IO * DIM_IO];
__device__ __half g_qh  [(size_t)NHOST  * DIM_IO];   // query, pre-scaled 1/32
__device__ __half g_kh  [(size_t)NGUEST * DIM_IO];
__device__ __half g_vth [(size_t)DIM_IO * NGUEST];   // value^T
__device__ __half g_P   [(size_t)NHOST  * NGUEST];   // probs
__device__ float  g_S   [(size_t)NHOST  * NGUEST];   // logits

// ============================================================
// helpers
// ============================================================
__device__ __forceinline__ void cp_async16(void* dst_smem, const void* src) {
    uint32_t a;
    asm("{ .reg .u64 t; cvta.to.shared.u64 t, %1; cvt.u32.u64 %0, t; }" : "=r"(a) : "l"(dst_smem));
    asm volatile("cp.async.cg.shared.global [%0], [%1], 16;" :: "r"(a), "l"(src) : "memory");
}
__device__ __forceinline__ void cp_commit() { asm volatile("cp.async.commit_group;" ::: "memory"); }
template <int N> __device__ __forceinline__ void cp_wait() {
    asm volatile("cp.async.wait_group %0;" :: "n"(N) : "memory");
}

// ============================================================
// fp16 WMMA GEMM: C[M,N] = alpha * A[M,K] @ B^T  (A:[M,K], B:[N,K])
// BM=128, BN=128, BK=64. 4 warps, warp tile 64x64 (4x4 frags).
// 3-stage cp.async pipeline. 2 CTAs/SM.
// ============================================================
#define BM 128
#define BN 128
#define BKG 64
#define LDT 72
#define STAGE_HALFS (2 * BM * LDT)                    // 18432 halfs = 36864 B
#define NSTAGES 3
#define GEMM_SMEM_BYTES (NSTAGES * STAGE_HALFS * 2)   // 110592

template <typename OutT>
__global__ void __launch_bounds__(128, 2)
gemm_h(const __half* __restrict__ A, const __half* __restrict__ B,
       OutT* __restrict__ C, int M, int N, int K, float alpha)
{
    extern __shared__ __align__(16) __half smem[];

    const int tid = threadIdx.x;
    const int wid = tid >> 5;
    const int wm  = wid >> 1;     // 0..1 -> 64-row slice
    const int wn  = wid & 1;      // 0..1 -> 64-col slice
    const int bm0 = blockIdx.y * BM;
    const int bn0 = blockIdx.x * BN;
    const int niter = K / BKG;

    using FragA  = wmma::fragment<wmma::matrix_a, 16, 16, 16, __half, wmma::row_major>;
    using FragB  = wmma::fragment<wmma::matrix_b, 16, 16, 16, __half, wmma::col_major>;
    using FragC  = wmma::fragment<wmma::accumulator, 16, 16, 16, float>;
    using FragCH = wmma::fragment<wmma::accumulator, 16, 16, 16, __half>;

    FragC acc[4][4];
    #pragma unroll
    for (int i = 0; i < 4; i++)
        #pragma unroll
        for (int j = 0; j < 4; j++)
            wmma::fill_fragment(acc[i][j], 0.0f);

    auto load_stage = [&](int s, int kit) {
        __half* As = smem + s * STAGE_HALFS;
        __half* Bs = As + BM * LDT;
        const int k0 = kit * BKG;
        #pragma unroll
        for (int t = 0; t < 8; t++) {
            int idx = tid + t * 128;          // 0..1023
            int r = idx >> 3;
            int c = (idx & 7) << 3;           // half col 0..56
            cp_async16(As + r * LDT + c, A + (size_t)(bm0 + r) * K + k0 + c);
        }
        #pragma unroll
        for (int t = 0; t < 8; t++) {
            int idx = tid + t * 128;
            int r = idx >> 3;
            int c = (idx & 7) << 3;
            cp_async16(Bs + r * LDT + c, B + (size_t)(bn0 + r) * K + k0 + c);
        }
        cp_commit();
    };

    load_stage(0, 0);
    if (niter > 1) load_stage(1, 1);

    for (int i = 0; i < niter; i++) {
        if (i + 2 < niter) {
            load_stage((i + 2) % NSTAGES, i + 2);
            cp_wait<2>();
        } else if (i + 1 < niter) {
            cp_wait<1>();
        } else {
            cp_wait<0>();
        }
        __syncthreads();

        const __half* As = smem + (i % NSTAGES) * STAGE_HALFS;
        const __half* Bs = As + BM * LDT;

        #pragma unroll
        for (int kk = 0; kk < BKG; kk += 16) {
            FragA af[4];
            FragB bf[4];
            #pragma unroll
            for (int x = 0; x < 4; x++)
                wmma::load_matrix_sync(af[x], As + (wm * 64 + x * 16) * LDT + kk, LDT);
            #pragma unroll
            for (int j = 0; j < 4; j++)
                wmma::load_matrix_sync(bf[j], Bs + (wn * 64 + j * 16) * LDT + kk, LDT);
            #pragma unroll
            for (int x = 0; x < 4; x++)
                #pragma unroll
                for (int j = 0; j < 4; j++)
                    wmma::mma_sync(acc[x][j], af[x], bf[j], acc[x][j]);
        }
        __syncthreads();
    }

    #pragma unroll
    for (int x = 0; x < 4; x++) {
        #pragma unroll
        for (int j = 0; j < 4; j++) {
            int row = bm0 + wm * 64 + x * 16;
            int col = bn0 + wn * 64 + j * 16;
            if constexpr (sizeof(OutT) == 2) {
                FragCH h;
                #pragma unroll
                for (int e = 0; e < acc[x][j].num_elements; e++)
                    h.x[e] = __float2half_rn(acc[x][j].x[e] * alpha);
                wmma::store_matrix_sync((__half*)&C[(size_t)row * N + col], h, N, wmma::mem_row_major);
            } else {
                #pragma unroll
                for (int e = 0; e < acc[x][j].num_elements; e++)
                    acc[x][j].x[e] *= alpha;
                wmma::store_matrix_sync((float*)&C[(size_t)row * N + col], acc[x][j], N, wmma::mem_row_major);
            }
        }
    }
}

// ============================================================
// fp32 -> fp16 convert with scale
// ============================================================
__global__ void __launch_bounds__(256)
f32_to_f16(const float4* __restrict__ in, __half2* __restrict__ out, int n4, float s)
{
    int i = blockIdx.x * 256 + threadIdx.x;
    if (i < n4) {
        float4 v = in[i];
        out[2 * i]     = __floats2half2_rn(v.x * s, v.y * s);
        out[2 * i + 1] = __floats2half2_rn(v.z * s, v.w * s);
    }
}

// ============================================================
// weight transpose (1024x1024) fp32 -> fp16
// ============================================================
__global__ void __launch_bounds__(256)
transpose_h(const float* __restrict__ in, __half* __restrict__ out)
{
    __shared__ float t[32][33];
    int x = blockIdx.x * 32 + threadIdx.x;
    int y = blockIdx.y * 32 + threadIdx.y;
    #pragma unroll
    for (int j = 0; j < 32; j += 8)
        t[threadIdx.y + j][threadIdx.x] = in[(size_t)(y + j) * DIM_IO + x];
    __syncthreads();
    x = blockIdx.y * 32 + threadIdx.x;
    y = blockIdx.x * 32 + threadIdx.y;
    #pragma unroll
    for (int j = 0; j < 32; j += 8)
        out[(size_t)(y + j) * DIM_IO + x] = __float2half_rn(t[threadIdx.x][threadIdx.y + j]);
}

// ============================================================
// Row softmax: fp32 logits -> fp16 probs
// ============================================================
__global__ void __launch_bounds__(256)
softmax_rows(const float* __restrict__ S, __half* __restrict__ P, int Ncols)
{
    __shared__ float buf[NGUEST];
    __shared__ float redm[8];
    __shared__ float reds[8];

    const int tid = threadIdx.x;
    const float* row = S + (size_t)blockIdx.x * Ncols;
    __half* prow = P + (size_t)blockIdx.x * Ncols;

    float lmax = -1e30f;
    for (int i = tid; i < Ncols; i += 256) {
        float v = row[i];
        buf[i] = v;
        lmax = fmaxf(lmax, v);
    }
    #pragma unroll
    for (int o = 16; o; o >>= 1)
        lmax = fmaxf(lmax, __shfl_xor_sync(0xffffffffu, lmax, o));
    if ((tid & 31) == 0) redm[tid >> 5] = lmax;
    __syncthreads();

    float m = redm[0];
    #pragma unroll
    for (int i = 1; i < 8; i++) m = fmaxf(m, redm[i]);

    float lsum = 0.0f;
    for (int i = tid; i < Ncols; i += 256) {
        float e = __expf(buf[i] - m);
        buf[i] = e;
        lsum += e;
    }
    #pragma unroll
    for (int o = 16; o; o >>= 1)
        lsum += __shfl_xor_sync(0xffffffffu, lsum, o);
    if ((tid & 31) == 0) reds[tid >> 5] = lsum;
    __syncthreads();

    float s = reds[0];
    #pragma unroll
    for (int i = 1; i < 8; i++) s += reds[i];
    float inv = 1.0f / s;

    for (int i = tid; i < Ncols; i += 256)
        prow[i] = __float2half_rn(buf[i] * inv);
}

// ============================================================
// launch
// ============================================================
extern "C" void kernel_launch(void* const* d_in, const int* in_sizes, int n_in,
                              void* d_out, int out_size)
{
    const float* fh = (const float*)d_in[0];
    const float* fg = (const float*)d_in[1];
    const float* Qw = (const float*)d_in[2];
    const float* Kw = (const float*)d_in[3];
    const float* Vw = (const float*)d_in[4];
    float* out = (float*)d_out;

    void *p;
    cudaGetSymbolAddress(&p, g_fh);  __half* hfh  = (__half*)p;
    cudaGetSymbolAddress(&p, g_fg);  __half* hfg  = (__half*)p;
    cudaGetSymbolAddress(&p, g_QwT); __half* hQwT = (__half*)p;
    cudaGetSymbolAddress(&p, g_KwT); __half* hKwT = (__half*)p;
    cudaGetSymbolAddress(&p, g_VwT); __half* hVwT = (__half*)p;
    cudaGetSymbolAddress(&p, g_qh);  __half* hq   = (__half*)p;
    cudaGetSymbolAddress(&p, g_kh);  __half* hk   = (__half*)p;
    cudaGetSymbolAddress(&p, g_vth); __half* hvt  = (__half*)p;
    cudaGetSymbolAddress(&p, g_P);   __half* hP   = (__half*)p;
    cudaGetSymbolAddress(&p, g_S);   float*  dS   = (float*)p;

    cudaFuncSetAttribute(gemm_h<float>,  cudaFuncAttributeMaxDynamicSharedMemorySize, GEMM_SMEM_BYTES);
    cudaFuncSetAttribute(gemm_h<__half>, cudaFuncAttributeMaxDynamicSharedMemorySize, GEMM_SMEM_BYTES);

    const float scale = 1.0f / 32.0f;

    f32_to_f16<<<NHOST  * DIM_IO / 4 / 256, 256>>>((const float4*)fh, (__half2*)hfh, NHOST  * DIM_IO / 4, 1.0f);
    f32_to_f16<<<NGUEST * DIM_IO / 4 / 256, 256>>>((const float4*)fg, (__half2*)hfg, NGUEST * DIM_IO / 4, 1.0f);

    dim3 tb(32, 8), tg(32, 32);
    transpose_h<<<tg, tb>>>(Qw, hQwT);
    transpose_h<<<tg, tb>>>(Kw, hKwT);
    transpose_h<<<tg, tb>>>(Vw, hVwT);

    gemm_h<__half><<<dim3(DIM_IO / BN, NHOST / BM), 128, GEMM_SMEM_BYTES>>>(
        hfh, hQwT, hq, NHOST, DIM_IO, DIM_IO, scale);
    gemm_h<__half><<<dim3(DIM_IO / BN, NGUEST / BM), 128, GEMM_SMEM_BYTES>>>(
        hfg, hKwT, hk, NGUEST, DIM_IO, DIM_IO, 1.0f);
    gemm_h<__half><<<dim3(NGUEST / BN, DIM_IO / BM), 128, GEMM_SMEM_BYTES>>>(
        hVwT, hfg, hvt, DIM_IO, NGUEST, DIM_IO, 1.0f);
    gemm_h<float><<<dim3(NGUEST / BN, NHOST / BM), 128, GEMM_SMEM_BYTES>>>(
        hq, hk, dS, NHOST, NGUEST, DIM_IO, 1.0f);
    softmax_rows<<<NHOST, 256>>>(dS, hP, NGUEST);
    gemm_h<float><<<dim3(DIM_IO / BN, NHOST / BM), 128, GEMM_SMEM_BYTES>>>(
        hP, hvt, out, NHOST, DIM_IO, NGUEST, 1.0f);
}

// round 7
// speedup vs baseline: 5.3452x; 1.0211x over previous
#include <cuda_runtime.h>
#include <cuda_fp16.h>
#include <mma.h>
#include <cstdint>

using namespace nvcuda;

#define DIM_IO   1024
#define NHOST    4096
#define NGUEST   8192

// -------- scratch (device globals: allocation-free) --------
__device__ __half g_fh  [(size_t)NHOST  * DIM_IO];
__device__ __half g_fg  [(size_t)NGUEST * DIM_IO];
__device__ __half g_QwT [(size_t)DIM_IO * DIM_IO];
__device__ __half g_KwT [(size_t)DIM_IO * DIM_IO];
__device__ __half g_VwT [(size_t)DIM_IO * DIM_IO];
__device__ __half g_qh  [(size_t)NHOST  * DIM_IO];   // query, pre-scaled 1/32
__device__ __half g_kh  [(size_t)NGUEST * DIM_IO];
__device__ __half g_vth [(size_t)DIM_IO * NGUEST];   // value^T
__device__ __half g_P   [(size_t)NHOST  * NGUEST];   // probs
__device__ float  g_S   [(size_t)NHOST  * NGUEST];   // logits

// ============================================================
// helpers
// ============================================================
__device__ __forceinline__ void cp_async16(void* dst_smem, const void* src) {
    uint32_t a;
    asm("{ .reg .u64 t; cvta.to.shared.u64 t, %1; cvt.u32.u64 %0, t; }" : "=r"(a) : "l"(dst_smem));
    asm volatile("cp.async.cg.shared.global [%0], [%1], 16;" :: "r"(a), "l"(src) : "memory");
}
__device__ __forceinline__ void cp_commit() { asm volatile("cp.async.commit_group;" ::: "memory"); }
template <int N> __device__ __forceinline__ void cp_wait() {
    asm volatile("cp.async.wait_group %0;" :: "n"(N) : "memory");
}

// ============================================================
// fp16 WMMA GEMM: C[M,N] = alpha * A[M,K] @ B^T  (A:[M,K], B:[N,K])
// BM=128, BN=128, BK=64. 4 warps, warp tile 64x64 (4x4 frags).
// Canonical 3-stage cp.async pipeline: 1 barrier / k-iter, each chunk
// loaded exactly once. 2 CTAs/SM.
// ============================================================
#define BM 128
#define BN 128
#define BKG 64
#define LDT 72
#define STAGE_HALFS (2 * BM * LDT)                    // 18432 halfs = 36864 B
#define NSTAGES 3
#define GEMM_SMEM_BYTES (NSTAGES * STAGE_HALFS * 2)   // 110592

template <typename OutT>
__global__ void __launch_bounds__(128, 2)
gemm_h(const __half* __restrict__ A, const __half* __restrict__ B,
       OutT* __restrict__ C, int M, int N, int K, float alpha)
{
    extern __shared__ __align__(16) __half smem[];

    const int tid = threadIdx.x;
    const int wid = tid >> 5;
    const int wm  = wid >> 1;     // 0..1 -> 64-row slice
    const int wn  = wid & 1;      // 0..1 -> 64-col slice
    const int bm0 = blockIdx.y * BM;
    const int bn0 = blockIdx.x * BN;
    const int niter = K / BKG;

    using FragA  = wmma::fragment<wmma::matrix_a, 16, 16, 16, __half, wmma::row_major>;
    using FragB  = wmma::fragment<wmma::matrix_b, 16, 16, 16, __half, wmma::col_major>;
    using FragC  = wmma::fragment<wmma::accumulator, 16, 16, 16, float>;
    using FragCH = wmma::fragment<wmma::accumulator, 16, 16, 16, __half>;

    FragC acc[4][4];
    #pragma unroll
    for (int i = 0; i < 4; i++)
        #pragma unroll
        for (int j = 0; j < 4; j++)
            wmma::fill_fragment(acc[i][j], 0.0f);

    auto load_stage = [&](int s, int kit) {
        __half* As = smem + s * STAGE_HALFS;
        __half* Bs = As + BM * LDT;
        const int k0 = kit * BKG;
        #pragma unroll
        for (int t = 0; t < 8; t++) {
            int idx = tid + t * 128;          // 0..1023
            int r = idx >> 3;
            int c = (idx & 7) << 3;           // half col 0..56
            cp_async16(As + r * LDT + c, A + (size_t)(bm0 + r) * K + k0 + c);
        }
        #pragma unroll
        for (int t = 0; t < 8; t++) {
            int idx = tid + t * 128;
            int r = idx >> 3;
            int c = (idx & 7) << 3;
            cp_async16(Bs + r * LDT + c, B + (size_t)(bn0 + r) * K + k0 + c);
        }
        cp_commit();
    };

    load_stage(0, 0);
    if (niter > 1) load_stage(1, 1);

    for (int i = 0; i < niter; i++) {
        // chunk i resident after this wait (≤1 younger group may remain in flight)
        if (i + 1 < niter) cp_wait<1>(); else cp_wait<0>();
        __syncthreads();   // all warps done reading stage (i-1)%3

        // prefetch chunk i+2 into stage (i+2)%3 == (i-1)%3 (idle now);
        // issued before compute so cp.async overlaps the MMAs.
        if (i + 2 < niter) load_stage((i + 2) % NSTAGES, i + 2);

        const __half* As = smem + (i % NSTAGES) * STAGE_HALFS;
        const __half* Bs = As + BM * LDT;

        #pragma unroll
        for (int kk = 0; kk < BKG; kk += 16) {
            FragA af[4];
            FragB bf[4];
            #pragma unroll
            for (int x = 0; x < 4; x++)
                wmma::load_matrix_sync(af[x], As + (wm * 64 + x * 16) * LDT + kk, LDT);
            #pragma unroll
            for (int j = 0; j < 4; j++)
                wmma::load_matrix_sync(bf[j], Bs + (wn * 64 + j * 16) * LDT + kk, LDT);
            #pragma unroll
            for (int x = 0; x < 4; x++)
                #pragma unroll
                for (int j = 0; j < 4; j++)
                    wmma::mma_sync(acc[x][j], af[x], bf[j], acc[x][j]);
        }
    }

    __syncthreads();   // protect smem (none reused, but cheap)

    #pragma unroll
    for (int x = 0; x < 4; x++) {
        #pragma unroll
        for (int j = 0; j < 4; j++) {
            int row = bm0 + wm * 64 + x * 16;
            int col = bn0 + wn * 64 + j * 16;
            if constexpr (sizeof(OutT) == 2) {
                FragCH h;
                #pragma unroll
                for (int e = 0; e < acc[x][j].num_elements; e++)
                    h.x[e] = __float2half_rn(acc[x][j].x[e] * alpha);
                wmma::store_matrix_sync((__half*)&C[(size_t)row * N + col], h, N, wmma::mem_row_major);
            } else {
                #pragma unroll
                for (int e = 0; e < acc[x][j].num_elements; e++)
                    acc[x][j].x[e] *= alpha;
                wmma::store_matrix_sync((float*)&C[(size_t)row * N + col], acc[x][j], N, wmma::mem_row_major);
            }
        }
    }
}

// ============================================================
// fp32 -> fp16 convert with scale
// ============================================================
__global__ void __launch_bounds__(256)
f32_to_f16(const float4* __restrict__ in, __half2* __restrict__ out, int n4, float s)
{
    int i = blockIdx.x * 256 + threadIdx.x;
    if (i < n4) {
        float4 v = in[i];
        out[2 * i]     = __floats2half2_rn(v.x * s, v.y * s);
        out[2 * i + 1] = __floats2half2_rn(v.z * s, v.w * s);
    }
}

// ============================================================
// weight transpose (1024x1024) fp32 -> fp16
// ============================================================
__global__ void __launch_bounds__(256)
transpose_h(const float* __restrict__ in, __half* __restrict__ out)
{
    __shared__ float t[32][33];
    int x = blockIdx.x * 32 + threadIdx.x;
    int y = blockIdx.y * 32 + threadIdx.y;
    #pragma unroll
    for (int j = 0; j < 32; j += 8)
        t[threadIdx.y + j][threadIdx.x] = in[(size_t)(y + j) * DIM_IO + x];
    __syncthreads();
    x = blockIdx.y * 32 + threadIdx.x;
    y = blockIdx.x * 32 + threadIdx.y;
    #pragma unroll
    for (int j = 0; j < 32; j += 8)
        out[(size_t)(y + j) * DIM_IO + x] = __float2half_rn(t[threadIdx.x][threadIdx.y + j]);
}

// ============================================================
// Row softmax: fp32 logits -> fp16 probs
// ============================================================
__global__ void __launch_bounds__(256)
softmax_rows(const float* __restrict__ S, __half* __restrict__ P, int Ncols)
{
    __shared__ float buf[NGUEST];
    __shared__ float redm[8];
    __shared__ float reds[8];

    const int tid = threadIdx.x;
    const float* row = S + (size_t)blockIdx.x * Ncols;
    __half* prow = P + (size_t)blockIdx.x * Ncols;

    float lmax = -1e30f;
    for (int i = tid; i < Ncols; i += 256) {
        float v = row[i];
        buf[i] = v;
        lmax = fmaxf(lmax, v);
    }
    #pragma unroll
    for (int o = 16; o; o >>= 1)
        lmax = fmaxf(lmax, __shfl_xor_sync(0xffffffffu, lmax, o));
    if ((tid & 31) == 0) redm[tid >> 5] = lmax;
    __syncthreads();

    float m = redm[0];
    #pragma unroll
    for (int i = 1; i < 8; i++) m = fmaxf(m, redm[i]);

    float lsum = 0.0f;
    for (int i = tid; i < Ncols; i += 256) {
        float e = __expf(buf[i] - m);
        buf[i] = e;
        lsum += e;
    }
    #pragma unroll
    for (int o = 16; o; o >>= 1)
        lsum += __shfl_xor_sync(0xffffffffu, lsum, o);
    if ((tid & 31) == 0) reds[tid >> 5] = lsum;
    __syncthreads();

    float s = reds[0];
    #pragma unroll
    for (int i = 1; i < 8; i++) s += reds[i];
    float inv = 1.0f / s;

    for (int i = tid; i < Ncols; i += 256)
        prow[i] = __float2half_rn(buf[i] * inv);
}

// ============================================================
// launch
// ============================================================
extern "C" void kernel_launch(void* const* d_in, const int* in_sizes, int n_in,
                              void* d_out, int out_size)
{
    const float* fh = (const float*)d_in[0];
    const float* fg = (const float*)d_in[1];
    const float* Qw = (const float*)d_in[2];
    const float* Kw = (const float*)d_in[3];
    const float* Vw = (const float*)d_in[4];
    float* out = (float*)d_out;

    void *p;
    cudaGetSymbolAddress(&p, g_fh);  __half* hfh  = (__half*)p;
    cudaGetSymbolAddress(&p, g_fg);  __half* hfg  = (__half*)p;
    cudaGetSymbolAddress(&p, g_QwT); __half* hQwT = (__half*)p;
    cudaGetSymbolAddress(&p, g_KwT); __half* hKwT = (__half*)p;
    cudaGetSymbolAddress(&p, g_VwT); __half* hVwT = (__half*)p;
    cudaGetSymbolAddress(&p, g_qh);  __half* hq   = (__half*)p;
    cudaGetSymbolAddress(&p, g_kh);  __half* hk   = (__half*)p;
    cudaGetSymbolAddress(&p, g_vth); __half* hvt  = (__half*)p;
    cudaGetSymbolAddress(&p, g_P);   __half* hP   = (__half*)p;
    cudaGetSymbolAddress(&p, g_S);   float*  dS   = (float*)p;

    cudaFuncSetAttribute(gemm_h<float>,  cudaFuncAttributeMaxDynamicSharedMemorySize, GEMM_SMEM_BYTES);
    cudaFuncSetAttribute(gemm_h<__half>, cudaFuncAttributeMaxDynamicSharedMemorySize, GEMM_SMEM_BYTES);

    const float scale = 1.0f / 32.0f;

    f32_to_f16<<<NHOST  * DIM_IO / 4 / 256, 256>>>((const float4*)fh, (__half2*)hfh, NHOST  * DIM_IO / 4, 1.0f);
    f32_to_f16<<<NGUEST * DIM_IO / 4 / 256, 256>>>((const float4*)fg, (__half2*)hfg, NGUEST * DIM_IO / 4, 1.0f);

    dim3 tb(32, 8), tg(32, 32);
    transpose_h<<<tg, tb>>>(Qw, hQwT);
    transpose_h<<<tg, tb>>>(Kw, hKwT);
    transpose_h<<<tg, tb>>>(Vw, hVwT);

    gemm_h<__half><<<dim3(DIM_IO / BN, NHOST / BM), 128, GEMM_SMEM_BYTES>>>(
        hfh, hQwT, hq, NHOST, DIM_IO, DIM_IO, scale);
    gemm_h<__half><<<dim3(DIM_IO / BN, NGUEST / BM), 128, GEMM_SMEM_BYTES>>>(
        hfg, hKwT, hk, NGUEST, DIM_IO, DIM_IO, 1.0f);
    gemm_h<__half><<<dim3(NGUEST / BN, DIM_IO / BM), 128, GEMM_SMEM_BYTES>>>(
        hVwT, hfg, hvt, DIM_IO, NGUEST, DIM_IO, 1.0f);
    gemm_h<float><<<dim3(NGUEST / BN, NHOST / BM), 128, GEMM_SMEM_BYTES>>>(
        hq, hk, dS, NHOST, NGUEST, DIM_IO, 1.0f);
    softmax_rows<<<NHOST, 256>>>(dS, hP, NGUEST);
    gemm_h<float><<<dim3(DIM_IO / BN, NHOST / BM), 128, GEMM_SMEM_BYTES>>>(
        hP, hvt, out, NHOST, DIM_IO, NGUEST, 1.0f);
}

// round 8
// speedup vs baseline: 5.7474x; 1.0753x over previous
#include <cuda_runtime.h>
#include <cuda_fp16.h>
#include <mma.h>
#include <cstdint>

using namespace nvcuda;

#define DIM_IO   1024
#define NHOST    4096
#define NGUEST   8192

// -------- scratch (device globals: allocation-free) --------
__device__ __half g_fh  [(size_t)NHOST  * DIM_IO];
__device__ __half g_fg  [(size_t)NGUEST * DIM_IO];
__device__ __half g_QwT [(size_t)DIM_IO * DIM_IO];
__device__ __half g_KwT [(size_t)DIM_IO * DIM_IO];
__device__ __half g_VwT [(size_t)DIM_IO * DIM_IO];
__device__ __half g_qh  [(size_t)NHOST  * DIM_IO];   // query, pre-scaled 1/32
__device__ __half g_kh  [(size_t)NGUEST * DIM_IO];
__device__ __half g_vth [(size_t)DIM_IO * NGUEST];   // value^T
__device__ __half g_P   [(size_t)NHOST  * NGUEST];   // probs
__device__ float  g_S   [(size_t)NHOST  * NGUEST];   // logits

// ============================================================
// helpers
// ============================================================
__device__ __forceinline__ void cp_async16(void* dst_smem, const void* src) {
    uint32_t a;
    asm("{ .reg .u64 t; cvta.to.shared.u64 t, %1; cvt.u32.u64 %0, t; }" : "=r"(a) : "l"(dst_smem));
    asm volatile("cp.async.cg.shared.global [%0], [%1], 16;" :: "r"(a), "l"(src) : "memory");
}
__device__ __forceinline__ void cp_commit() { asm volatile("cp.async.commit_group;" ::: "memory"); }
template <int N> __device__ __forceinline__ void cp_wait() {
    asm volatile("cp.async.wait_group %0;" :: "n"(N) : "memory");
}

// ============================================================
// fp16 WMMA GEMM: C[M,N] = alpha * A[M,K] @ B^T  (A:[M,K], B:[N,K])
// BM=128, BN=128, BK=64. 4 warps, warp tile 64x64. 3-stage cp.async.
// ============================================================
#define BM 128
#define BN 128
#define BKG 64
#define LDT 72
#define STAGE_HALFS (2 * BM * LDT)
#define NSTAGES 3
#define GEMM_SMEM_BYTES (NSTAGES * STAGE_HALFS * 2)   // 110592

template <typename OutT>
__global__ void __launch_bounds__(128, 2)
gemm_h(const __half* __restrict__ A, const __half* __restrict__ B,
       OutT* __restrict__ C, int M, int N, int K, float alpha)
{
    extern __shared__ __align__(16) __half smem[];

    const int tid = threadIdx.x;
    const int wid = tid >> 5;
    const int wm  = wid >> 1;
    const int wn  = wid & 1;
    const int bm0 = blockIdx.y * BM;
    const int bn0 = blockIdx.x * BN;
    const int niter = K / BKG;

    using FragA  = wmma::fragment<wmma::matrix_a, 16, 16, 16, __half, wmma::row_major>;
    using FragB  = wmma::fragment<wmma::matrix_b, 16, 16, 16, __half, wmma::col_major>;
    using FragC  = wmma::fragment<wmma::accumulator, 16, 16, 16, float>;
    using FragCH = wmma::fragment<wmma::accumulator, 16, 16, 16, __half>;

    FragC acc[4][4];
    #pragma unroll
    for (int i = 0; i < 4; i++)
        #pragma unroll
        for (int j = 0; j < 4; j++)
            wmma::fill_fragment(acc[i][j], 0.0f);

    auto load_stage = [&](int s, int kit) {
        __half* As = smem + s * STAGE_HALFS;
        __half* Bs = As + BM * LDT;
        const int k0 = kit * BKG;
        #pragma unroll
        for (int t = 0; t < 8; t++) {
            int idx = tid + t * 128;
            int r = idx >> 3;
            int c = (idx & 7) << 3;
            cp_async16(As + r * LDT + c, A + (size_t)(bm0 + r) * K + k0 + c);
        }
        #pragma unroll
        for (int t = 0; t < 8; t++) {
            int idx = tid + t * 128;
            int r = idx >> 3;
            int c = (idx & 7) << 3;
            cp_async16(Bs + r * LDT + c, B + (size_t)(bn0 + r) * K + k0 + c);
        }
        cp_commit();
    };

    load_stage(0, 0);
    if (niter > 1) load_stage(1, 1);

    for (int i = 0; i < niter; i++) {
        if (i + 1 < niter) cp_wait<1>(); else cp_wait<0>();
        __syncthreads();

        if (i + 2 < niter) load_stage((i + 2) % NSTAGES, i + 2);

        const __half* As = smem + (i % NSTAGES) * STAGE_HALFS;
        const __half* Bs = As + BM * LDT;

        #pragma unroll
        for (int kk = 0; kk < BKG; kk += 16) {
            FragA af[4];
            FragB bf[4];
            #pragma unroll
            for (int x = 0; x < 4; x++)
                wmma::load_matrix_sync(af[x], As + (wm * 64 + x * 16) * LDT + kk, LDT);
            #pragma unroll
            for (int j = 0; j < 4; j++)
                wmma::load_matrix_sync(bf[j], Bs + (wn * 64 + j * 16) * LDT + kk, LDT);
            #pragma unroll
            for (int x = 0; x < 4; x++)
                #pragma unroll
                for (int j = 0; j < 4; j++)
                    wmma::mma_sync(acc[x][j], af[x], bf[j], acc[x][j]);
        }
    }

    __syncthreads();

    #pragma unroll
    for (int x = 0; x < 4; x++) {
        #pragma unroll
        for (int j = 0; j < 4; j++) {
            int row = bm0 + wm * 64 + x * 16;
            int col = bn0 + wn * 64 + j * 16;
            if constexpr (sizeof(OutT) == 2) {
                FragCH h;
                #pragma unroll
                for (int e = 0; e < acc[x][j].num_elements; e++)
                    h.x[e] = __float2half_rn(acc[x][j].x[e] * alpha);
                wmma::store_matrix_sync((__half*)&C[(size_t)row * N + col], h, N, wmma::mem_row_major);
            } else {
                #pragma unroll
                for (int e = 0; e < acc[x][j].num_elements; e++)
                    acc[x][j].x[e] *= alpha;
                wmma::store_matrix_sync((float*)&C[(size_t)row * N + col], acc[x][j], N, wmma::mem_row_major);
            }
        }
    }
}

// ============================================================
// fp32 -> fp16 convert with scale
// ============================================================
__global__ void __launch_bounds__(256)
f32_to_f16(const float4* __restrict__ in, __half2* __restrict__ out, int n4, float s)
{
    int i = blockIdx.x * 256 + threadIdx.x;
    if (i < n4) {
        float4 v = in[i];
        out[2 * i]     = __floats2half2_rn(v.x * s, v.y * s);
        out[2 * i + 1] = __floats2half2_rn(v.z * s, v.w * s);
    }
}

// ============================================================
// weight transpose (1024x1024) fp32 -> fp16
// ============================================================
__global__ void __launch_bounds__(256)
transpose_h(const float* __restrict__ in, __half* __restrict__ out)
{
    __shared__ float t[32][33];
    int x = blockIdx.x * 32 + threadIdx.x;
    int y = blockIdx.y * 32 + threadIdx.y;
    #pragma unroll
    for (int j = 0; j < 32; j += 8)
        t[threadIdx.y + j][threadIdx.x] = in[(size_t)(y + j) * DIM_IO + x];
    __syncthreads();
    x = blockIdx.y * 32 + threadIdx.x;
    y = blockIdx.x * 32 + threadIdx.y;
    #pragma unroll
    for (int j = 0; j < 32; j += 8)
        out[(size_t)(y + j) * DIM_IO + x] = __float2half_rn(t[threadIdx.x][threadIdx.y + j]);
}

// ============================================================
// Row softmax: fp32 logits -> fp16 probs
// ============================================================
__global__ void __launch_bounds__(256)
softmax_rows(const float* __restrict__ S, __half* __restrict__ P, int Ncols)
{
    __shared__ float buf[NGUEST];
    __shared__ float redm[8];
    __shared__ float reds[8];

    const int tid = threadIdx.x;
    const float* row = S + (size_t)blockIdx.x * Ncols;
    __half* prow = P + (size_t)blockIdx.x * Ncols;

    float lmax = -1e30f;
    for (int i = tid; i < Ncols; i += 256) {
        float v = row[i];
        buf[i] = v;
        lmax = fmaxf(lmax, v);
    }
    #pragma unroll
    for (int o = 16; o; o >>= 1)
        lmax = fmaxf(lmax, __shfl_xor_sync(0xffffffffu, lmax, o));
    if ((tid & 31) == 0) redm[tid >> 5] = lmax;
    __syncthreads();

    float m = redm[0];
    #pragma unroll
    for (int i = 1; i < 8; i++) m = fmaxf(m, redm[i]);

    float lsum = 0.0f;
    for (int i = tid; i < Ncols; i += 256) {
        float e = __expf(buf[i] - m);
        buf[i] = e;
        lsum += e;
    }
    #pragma unroll
    for (int o = 16; o; o >>= 1)
        lsum += __shfl_xor_sync(0xffffffffu, lsum, o);
    if ((tid & 31) == 0) reds[tid >> 5] = lsum;
    __syncthreads();

    float s = reds[0];
    #pragma unroll
    for (int i = 1; i < 8; i++) s += reds[i];
    float inv = 1.0f / s;

    for (int i = tid; i < Ncols; i += 256)
        prow[i] = __float2half_rn(buf[i] * inv);
}

// ============================================================
// one-time host-side stream/event setup (no device memory involved)
// ============================================================
struct Aux {
    cudaStream_t s1, s2;
    cudaEvent_t  e_root, e_fg, e_k, e_v;
    Aux() {
        cudaStreamCreateWithFlags(&s1, cudaStreamNonBlocking);
        cudaStreamCreateWithFlags(&s2, cudaStreamNonBlocking);
        cudaEventCreateWithFlags(&e_root, cudaEventDisableTiming);
        cudaEventCreateWithFlags(&e_fg,   cudaEventDisableTiming);
        cudaEventCreateWithFlags(&e_k,    cudaEventDisableTiming);
        cudaEventCreateWithFlags(&e_v,    cudaEventDisableTiming);
    }
};

// ============================================================
// launch
// ============================================================
extern "C" void kernel_launch(void* const* d_in, const int* in_sizes, int n_in,
                              void* d_out, int out_size)
{
    const float* fh = (const float*)d_in[0];
    const float* fg = (const float*)d_in[1];
    const float* Qw = (const float*)d_in[2];
    const float* Kw = (const float*)d_in[3];
    const float* Vw = (const float*)d_in[4];
    float* out = (float*)d_out;

    void *p;
    cudaGetSymbolAddress(&p, g_fh);  __half* hfh  = (__half*)p;
    cudaGetSymbolAddress(&p, g_fg);  __half* hfg  = (__half*)p;
    cudaGetSymbolAddress(&p, g_QwT); __half* hQwT = (__half*)p;
    cudaGetSymbolAddress(&p, g_KwT); __half* hKwT = (__half*)p;
    cudaGetSymbolAddress(&p, g_VwT); __half* hVwT = (__half*)p;
    cudaGetSymbolAddress(&p, g_qh);  __half* hq   = (__half*)p;
    cudaGetSymbolAddress(&p, g_kh);  __half* hk   = (__half*)p;
    cudaGetSymbolAddress(&p, g_vth); __half* hvt  = (__half*)p;
    cudaGetSymbolAddress(&p, g_P);   __half* hP   = (__half*)p;
    cudaGetSymbolAddress(&p, g_S);   float*  dS   = (float*)p;

    cudaFuncSetAttribute(gemm_h<float>,  cudaFuncAttributeMaxDynamicSharedMemorySize, GEMM_SMEM_BYTES);
    cudaFuncSetAttribute(gemm_h<__half>, cudaFuncAttributeMaxDynamicSharedMemorySize, GEMM_SMEM_BYTES);

    static Aux ax;   // host-side objects, created once

    const float scale = 1.0f / 32.0f;
    dim3 tb(32, 8), tg(32, 32);

    // ---- fork ----
    cudaEventRecord(ax.e_root, 0);
    cudaStreamWaitEvent(ax.s1, ax.e_root, 0);
    cudaStreamWaitEvent(ax.s2, ax.e_root, 0);

    // s0: host features -> fp16, QwT, Q-proj
    f32_to_f16<<<NHOST * DIM_IO / 4 / 256, 256, 0, 0>>>(
        (const float4*)fh, (__half2*)hfh, NHOST * DIM_IO / 4, 1.0f);
    transpose_h<<<tg, tb, 0, 0>>>(Qw, hQwT);
    gemm_h<__half><<<dim3(DIM_IO / BN, NHOST / BM), 128, GEMM_SMEM_BYTES, 0>>>(
        hfh, hQwT, hq, NHOST, DIM_IO, DIM_IO, scale);

    // s1: guest features -> fp16, KwT, K-proj
    f32_to_f16<<<NGUEST * DIM_IO / 4 / 256, 256, 0, ax.s1>>>(
        (const float4*)fg, (__half2*)hfg, NGUEST * DIM_IO / 4, 1.0f);
    cudaEventRecord(ax.e_fg, ax.s1);
    transpose_h<<<tg, tb, 0, ax.s1>>>(Kw, hKwT);
    gemm_h<__half><<<dim3(DIM_IO / BN, NGUEST / BM), 128, GEMM_SMEM_BYTES, ax.s1>>>(
        hfg, hKwT, hk, NGUEST, DIM_IO, DIM_IO, 1.0f);
    cudaEventRecord(ax.e_k, ax.s1);

    // s2: VwT, V-proj (valT) — overlaps logits on s0
    cudaStreamWaitEvent(ax.s2, ax.e_fg, 0);
    transpose_h<<<tg, tb, 0, ax.s2>>>(Vw, hVwT);
    gemm_h<__half><<<dim3(NGUEST / BN, DIM_IO / BM), 128, GEMM_SMEM_BYTES, ax.s2>>>(
        hVwT, hfg, hvt, DIM_IO, NGUEST, DIM_IO, 1.0f);
    cudaEventRecord(ax.e_v, ax.s2);

    // s0: logits (needs Q-proj [s0] + K-proj [s1])
    cudaStreamWaitEvent(0, ax.e_k, 0);
    gemm_h<float><<<dim3(NGUEST / BN, NHOST / BM), 128, GEMM_SMEM_BYTES, 0>>>(
        hq, hk, dS, NHOST, NGUEST, DIM_IO, 1.0f);

    // s0: softmax -> fp16 probs
    softmax_rows<<<NHOST, 256, 0, 0>>>(dS, hP, NGUEST);

    // s0: out = P @ value (needs valT from s2)
    cudaStreamWaitEvent(0, ax.e_v, 0);
    gemm_h<float><<<dim3(DIM_IO / BN, NHOST / BM), 128, GEMM_SMEM_BYTES, 0>>>(
        hP, hvt, out, NHOST, DIM_IO, NGUEST, 1.0f);
}